// round 1
// baseline (speedup 1.0000x reference)
#include <cuda_runtime.h>

#define B 8
#define N 4096
#define D 1024
#define H 1024
#define NQ 64
#define H2 2048
#define TOPK 1024

// ---------------- scratch (device globals; no allocations allowed) ----------
__device__ float g_QW[D * NQ];          // [d][q]  query_embed @ key_w^T, transposed
__device__ float g_qb[NQ];              // q . key_b
__device__ float g_dbias[B * N];        // density bias per token
__device__ float g_S[B * NQ * N];       // scores [b][q][n]
__device__ float g_c[B * NQ];           // per-(b,q): max + log(sum exp)
__device__ float g_imp[B * N];          // importance surrogate (log-domain)
__device__ int   g_flag[B * N];         // selected flag
__device__ int   g_idx[B * TOPK];       // selected indices, ascending

// ---------------- kernel 1: QW[d][q] = sum_h qe[q][h]*kw[d][h]; qb ----------
__global__ void k_qw(const float* __restrict__ qe, const float* __restrict__ kw,
                     const float* __restrict__ kb) {
    __shared__ float ws[H];
    int d = blockIdx.x;                      // 0..D (D == key_b row)
    const float* src = (d < D) ? (kw + (size_t)d * H) : kb;
    for (int i = threadIdx.x; i < H / 4; i += blockDim.x)
        ((float4*)ws)[i] = ((const float4*)src)[i];
    __syncthreads();
    int q = threadIdx.x;                     // 64 threads
    const float* qr = qe + (size_t)q * H;
    float acc = 0.f;
#pragma unroll 8
    for (int h = 0; h < H; h++) acc = fmaf(qr[h], ws[h], acc);
    if (d < D) g_QW[d * NQ + q] = acc;
    else       g_qb[q] = acc;
}

// ---------------- kernel 2: density bias -----------------------------------
__global__ void k_dbias(const float* __restrict__ dens, const float* __restrict__ w1,
                        const float* __restrict__ b1, const float* __restrict__ w2,
                        const float* __restrict__ b2) {
    __shared__ float s1[H2], sb[H2], s2[H2];
    for (int i = threadIdx.x; i < H2; i += blockDim.x) {
        s1[i] = w1[i]; sb[i] = b1[i]; s2[i] = w2[i];
    }
    __syncthreads();
    int t = blockIdx.x * blockDim.x + threadIdx.x;   // token over B*N
    float dv = dens[t];
    float acc = 0.f;
#pragma unroll 4
    for (int j = 0; j < H2; j++) {
        float hv = fmaf(dv, s1[j], sb[j]);
        acc = fmaf(fmaxf(hv, 0.f), s2[j], acc);
    }
    g_dbias[t] = acc + b2[0];
}

// ---------------- kernel 3: score GEMM + bias -------------------------------
// Block: 64 tokens x 64 queries, full K=1024 loop, 256 threads, 4x4 reg tile.
__global__ void __launch_bounds__(256) k_score(const float* __restrict__ x) {
    __shared__ float sx[64][68];   // [d][n], padded
    __shared__ float sq[64][64];   // [d][q]
    int b  = blockIdx.y;
    int n0 = blockIdx.x * 64;
    int tid = threadIdx.x;
    int tx = tid & 15;             // query group
    int ty = tid >> 4;             // token group
    float acc[4][4] = {};
    const float* xb = x + ((size_t)(b * N + n0)) * D;

    for (int dt = 0; dt < D; dt += 64) {
#pragma unroll
        for (int r = 0; r < 4; r++) {
            int idx = tid + 256 * r;        // 0..1023
            int n   = idx >> 4;             // 0..63
            int dc  = idx & 15;             // float4 within 64-d chunk
            float4 v = *(const float4*)(xb + (size_t)n * D + dt + dc * 4);
            sx[dc * 4 + 0][n] = v.x;
            sx[dc * 4 + 1][n] = v.y;
            sx[dc * 4 + 2][n] = v.z;
            sx[dc * 4 + 3][n] = v.w;
        }
#pragma unroll
        for (int r = 0; r < 4; r++) {
            int idx = tid + 256 * r;
            int row = idx >> 4;
            int col = idx & 15;
            *(float4*)&sq[row][col * 4] =
                *(const float4*)(g_QW + (dt + row) * NQ + col * 4);
        }
        __syncthreads();
#pragma unroll
        for (int dd = 0; dd < 64; dd++) {
            float4 xa = *(float4*)&sx[dd][ty * 4];
            float4 qa = *(float4*)&sq[dd][tx * 4];
            acc[0][0] = fmaf(xa.x, qa.x, acc[0][0]);
            acc[0][1] = fmaf(xa.x, qa.y, acc[0][1]);
            acc[0][2] = fmaf(xa.x, qa.z, acc[0][2]);
            acc[0][3] = fmaf(xa.x, qa.w, acc[0][3]);
            acc[1][0] = fmaf(xa.y, qa.x, acc[1][0]);
            acc[1][1] = fmaf(xa.y, qa.y, acc[1][1]);
            acc[1][2] = fmaf(xa.y, qa.z, acc[1][2]);
            acc[1][3] = fmaf(xa.y, qa.w, acc[1][3]);
            acc[2][0] = fmaf(xa.z, qa.x, acc[2][0]);
            acc[2][1] = fmaf(xa.z, qa.y, acc[2][1]);
            acc[2][2] = fmaf(xa.z, qa.z, acc[2][2]);
            acc[2][3] = fmaf(xa.z, qa.w, acc[2][3]);
            acc[3][0] = fmaf(xa.w, qa.x, acc[3][0]);
            acc[3][1] = fmaf(xa.w, qa.y, acc[3][1]);
            acc[3][2] = fmaf(xa.w, qa.z, acc[3][2]);
            acc[3][3] = fmaf(xa.w, qa.w, acc[3][3]);
        }
        __syncthreads();
    }

    const float inv_scale = 0.03125f;   // 1/sqrt(1024)
#pragma unroll
    for (int j = 0; j < 4; j++) {
        int q = tx * 4 + j;
        float qbv = g_qb[q];
#pragma unroll
        for (int i = 0; i < 4; i++) {
            int n = n0 + ty * 4 + i;
            g_S[((b * NQ + q) << 12) + n] =
                (acc[i][j] + qbv) * inv_scale + g_dbias[b * N + n];
        }
    }
}

// ---------------- kernel 4: per-(b,q) c = max + log(sum exp) ----------------
__global__ void k_reduce() {
    int bq = blockIdx.x;                 // B*NQ
    const float* row = g_S + ((size_t)bq << 12);
    int tid = threadIdx.x;               // 256
    __shared__ float sm[8];

    float m = -1e30f;
    for (int i = tid; i < N; i += 256) m = fmaxf(m, row[i]);
#pragma unroll
    for (int o = 16; o; o >>= 1) m = fmaxf(m, __shfl_xor_sync(~0u, m, o));
    if ((tid & 31) == 0) sm[tid >> 5] = m;
    __syncthreads();
    if (tid < 32) {
        float v = (tid < 8) ? sm[tid] : -1e30f;
#pragma unroll
        for (int o = 4; o; o >>= 1) v = fmaxf(v, __shfl_xor_sync(~0u, v, o));
        if (tid == 0) sm[0] = v;
    }
    __syncthreads();
    m = sm[0];
    __syncthreads();

    float s = 0.f;
    for (int i = tid; i < N; i += 256) s += expf(row[i] - m);
#pragma unroll
    for (int o = 16; o; o >>= 1) s += __shfl_xor_sync(~0u, s, o);
    if ((tid & 31) == 0) sm[tid >> 5] = s;
    __syncthreads();
    if (tid == 0) {
        float z = 0.f;
#pragma unroll
        for (int w = 0; w < 8; w++) z += sm[w];
        g_c[bq] = m + logf(z);
    }
}

// ---------------- kernel 5: importance (log-domain, exp skipped) ------------
__global__ void k_imp() {
    __shared__ float sc[NQ];
    int t = blockIdx.x * 256 + threadIdx.x;   // over B*N; 16 blocks per batch
    int b = t >> 12;
    if (threadIdx.x < NQ) sc[threadIdx.x] = g_c[b * NQ + threadIdx.x];
    __syncthreads();
    int n = t & (N - 1);
    const float* Sp = g_S + ((size_t)(b * NQ) << 12) + n;
    float best = -1e30f;
#pragma unroll 8
    for (int q = 0; q < NQ; q++) best = fmaxf(best, Sp[q << 12] - sc[q]);
    g_imp[t] = best;
}

// ---------------- kernel 6: exact rank (stable top-k, JAX tie-break) --------
__global__ void __launch_bounds__(256) k_rank() {
    __shared__ unsigned long long key[N];
    int b   = blockIdx.x >> 4;
    int seg = blockIdx.x & 15;
    int tid = threadIdx.x;
    for (int i = tid; i < N; i += 256) {
        unsigned u = __float_as_uint(g_imp[b * N + i]);
        u ^= ((unsigned)(((int)u) >> 31)) | 0x80000000u;  // monotone float->uint
        key[i] = ((unsigned long long)u << 12) | (unsigned)(N - 1 - i);
    }
    __syncthreads();
    int i = seg * 256 + tid;
    unsigned long long ki = key[i];
    int r = 0;
#pragma unroll 8
    for (int j = 0; j < N; j++) r += (key[j] > ki);
    g_flag[b * N + i] = (r < TOPK) ? 1 : 0;
}

// ---------------- kernel 7: compact selected indices (ascending) ------------
__global__ void k_compact() {
    __shared__ unsigned words[N / 32];
    __shared__ int pre[N / 32];
    int b   = blockIdx.x;      // 8
    int tid = threadIdx.x;     // 1024
#pragma unroll
    for (int cc = 0; cc < N / 1024; cc++) {
        int gi = cc * 1024 + tid;
        unsigned bal = __ballot_sync(~0u, g_flag[b * N + gi]);
        if ((tid & 31) == 0) words[gi >> 5] = bal;
    }
    __syncthreads();
    if (tid == 0) {
        int s = 0;
        for (int w = 0; w < N / 32; w++) { pre[w] = s; s += __popc(words[w]); }
    }
    __syncthreads();
#pragma unroll
    for (int cc = 0; cc < N / 1024; cc++) {
        int gi = cc * 1024 + tid;
        unsigned w = words[gi >> 5];
        if ((w >> (gi & 31)) & 1u) {
            int slot = pre[gi >> 5] + __popc(w & ((1u << (gi & 31)) - 1u));
            g_idx[b * TOPK + slot] = gi;
        }
    }
}

// ---------------- kernel 8: gather selected rows ----------------------------
__global__ void k_gather(const float* __restrict__ x, float* __restrict__ out) {
    int row = blockIdx.x;             // B*TOPK
    int b   = row >> 10;
    int i   = g_idx[row];
    const float4* src = (const float4*)(x + ((size_t)(b * N + i)) * D);
    float4* dst = (float4*)(out + (size_t)row * D);
    dst[threadIdx.x] = src[threadIdx.x];   // 256 threads * 16B = 4KB row
}

// ---------------- launch ----------------------------------------------------
extern "C" void kernel_launch(void* const* d_in, const int* in_sizes, int n_in,
                              void* d_out, int out_size) {
    const float* tf   = (const float*)d_in[0];  // token_features [B,N,D]
    const float* dens = (const float*)d_in[1];  // token_densities [B,N]
    const float* qe   = (const float*)d_in[2];  // query_embed [NQ,H]
    const float* kw   = (const float*)d_in[3];  // key_w [D,H]
    const float* kb   = (const float*)d_in[4];  // key_b [H]
    const float* w1   = (const float*)d_in[5];  // de_w1 [1,2H]
    const float* b1   = (const float*)d_in[6];  // de_b1 [2H]
    const float* w2   = (const float*)d_in[7];  // de_w2 [2H,1]
    const float* b2   = (const float*)d_in[8];  // de_b2 [1]
    float* out = (float*)d_out;

    k_qw<<<D + 1, 64>>>(qe, kw, kb);
    k_dbias<<<B * N / 256, 256>>>(dens, w1, b1, w2, b2);
    dim3 gs(N / 64, B);
    k_score<<<gs, 256>>>(tf);
    k_reduce<<<B * NQ, 256>>>();
    k_imp<<<B * N / 256, 256>>>();
    k_rank<<<B * 16, 256>>>();
    k_compact<<<B, 1024>>>();
    k_gather<<<B * TOPK, 256>>>(tf, out);
}

// round 3
// speedup vs baseline: 1.9983x; 1.9983x over previous
#include <cuda_runtime.h>
#include <cuda_bf16.h>
#include <cstdint>

#define B 8
#define N 4096
#define D 1024
#define H 1024
#define NQ 64
#define H2 2048
#define TOPK 1024

// ---------------- scratch (device globals; no allocations allowed) ----------
__device__ __align__(16) __nv_bfloat16 g_QWb[3 * NQ * D]; // bf16 split planes [q][d]
__device__ float g_QWf[NQ * D];        // fp32 QW accumulator [q][d]
__device__ float g_qbi[NQ];            // qb*inv32 + b2
__device__ float g_dbias[B * N];       // density MLP sum (no b2)
__device__ float g_S[B * NQ * N];      // scores [b][q][n]
__device__ float g_pmax[B * 32 * NQ];  // per-tile per-q max
__device__ float g_psum[B * 32 * NQ];  // per-tile per-q sum exp
__device__ float g_c[B * NQ];          // logsumexp constants
__device__ float g_imp[B * N];
__device__ int   g_flag[B * N];
__device__ int   g_idx[B * TOPK];

// ---------------- helpers ----------------------------------------------------
__device__ __forceinline__ uint32_t packbf(float lo, float hi) {
    uint32_t r;
    asm("cvt.rn.bf16x2.f32 %0, %1, %2;" : "=r"(r) : "f"(hi), "f"(lo));
    return r;
}
__device__ __forceinline__ float loff(uint32_t p) { return __uint_as_float(p << 16); }
__device__ __forceinline__ float hiff(uint32_t p) { return __uint_as_float(p & 0xFFFF0000u); }

__device__ __forceinline__ void mma16816(float* d, const uint32_t* a, const uint32_t* b) {
    asm volatile("mma.sync.aligned.m16n8k16.row.col.f32.bf16.bf16.f32 "
        "{%0,%1,%2,%3}, {%4,%5,%6,%7}, {%8,%9}, {%0,%1,%2,%3};"
        : "+f"(d[0]), "+f"(d[1]), "+f"(d[2]), "+f"(d[3])
        : "r"(a[0]), "r"(a[1]), "r"(a[2]), "r"(a[3]), "r"(b[0]), "r"(b[1]));
}

// ---------------- kernel 0: init (qbi, zero accumulators) --------------------
__global__ void k_init(const float* __restrict__ qe, const float* __restrict__ kb,
                       const float* __restrict__ b2) {
    int tid = threadIdx.x;
    if (blockIdx.x == 0) {
        int w = tid >> 5, l = tid & 31;
        float b2v = b2[0];
#pragma unroll
        for (int qi = 0; qi < 8; qi++) {
            int q = w * 8 + qi;
            float acc = 0.f;
#pragma unroll
            for (int k = 0; k < 32; k++)
                acc = fmaf(qe[(size_t)q * H + k * 32 + l], kb[k * 32 + l], acc);
#pragma unroll
            for (int o = 16; o; o >>= 1) acc += __shfl_xor_sync(~0u, acc, o);
            if (l == 0) g_qbi[q] = acc * 0.03125f + b2v;
        }
    } else {
        int blk = blockIdx.x - 1;
        g_dbias[blk * 256 + tid] = 0.f;
        g_QWf[blk * 512 + tid] = 0.f;
        g_QWf[blk * 512 + 256 + tid] = 0.f;
    }
}

// ---------------- kernel 1: QW fp32 tiled GEMM (atomic over k-slabs) ---------
__global__ void __launch_bounds__(256) k_qw(const float* __restrict__ qe,
                                            const float* __restrict__ kw) {
    __shared__ float skw[64][68], sqe[64][68];
    int d0 = (blockIdx.x & 15) * 64;
    int k0 = (blockIdx.x >> 4) * 256;
    int tid = threadIdx.x;
    int tx = tid & 15, ty = tid >> 4;
    float acc[4][4] = {};
    for (int kc = 0; kc < 4; kc++) {
#pragma unroll
        for (int r = 0; r < 4; r++) {
            int idx = tid + 256 * r;
            int row = idx >> 4, c4 = (idx & 15) * 4;
            *(float4*)&skw[row][c4] = *(const float4*)(kw + (size_t)(d0 + row) * H + k0 + kc * 64 + c4);
            *(float4*)&sqe[row][c4] = *(const float4*)(qe + (size_t)row * H + k0 + kc * 64 + c4);
        }
        __syncthreads();
#pragma unroll 8
        for (int k = 0; k < 64; k++) {
            float a0 = skw[ty * 4 + 0][k], a1 = skw[ty * 4 + 1][k];
            float a2 = skw[ty * 4 + 2][k], a3 = skw[ty * 4 + 3][k];
            float q0 = sqe[tx * 4 + 0][k], q1 = sqe[tx * 4 + 1][k];
            float q2 = sqe[tx * 4 + 2][k], q3 = sqe[tx * 4 + 3][k];
            acc[0][0] = fmaf(a0, q0, acc[0][0]); acc[0][1] = fmaf(a0, q1, acc[0][1]);
            acc[0][2] = fmaf(a0, q2, acc[0][2]); acc[0][3] = fmaf(a0, q3, acc[0][3]);
            acc[1][0] = fmaf(a1, q0, acc[1][0]); acc[1][1] = fmaf(a1, q1, acc[1][1]);
            acc[1][2] = fmaf(a1, q2, acc[1][2]); acc[1][3] = fmaf(a1, q3, acc[1][3]);
            acc[2][0] = fmaf(a2, q0, acc[2][0]); acc[2][1] = fmaf(a2, q1, acc[2][1]);
            acc[2][2] = fmaf(a2, q2, acc[2][2]); acc[2][3] = fmaf(a2, q3, acc[2][3]);
            acc[3][0] = fmaf(a3, q0, acc[3][0]); acc[3][1] = fmaf(a3, q1, acc[3][1]);
            acc[3][2] = fmaf(a3, q2, acc[3][2]); acc[3][3] = fmaf(a3, q3, acc[3][3]);
        }
        __syncthreads();
    }
#pragma unroll
    for (int i = 0; i < 4; i++)
#pragma unroll
        for (int j = 0; j < 4; j++)
            atomicAdd(&g_QWf[(tx * 4 + j) * D + d0 + ty * 4 + i], acc[i][j]);
}

// ---------------- kernel 2: split QW into bf16 planes ------------------------
__global__ void k_split() {
    int t = blockIdx.x * 256 + threadIdx.x;       // < 65536
    float v = g_QWf[t];
    __nv_bfloat16 b0 = __float2bfloat16_rn(v);
    float r1 = v - __bfloat162float(b0);
    __nv_bfloat16 b1 = __float2bfloat16_rn(r1);
    float r2 = r1 - __bfloat162float(b1);
    g_QWb[t] = b0;
    g_QWb[65536 + t] = b1;
    g_QWb[131072 + t] = __float2bfloat16_rn(r2);
}

// ---------------- kernel 3: density bias (j-chunk x token-group, atomic) -----
__global__ void __launch_bounds__(256) k_dbias(const float* __restrict__ dens,
                                               const float* __restrict__ w1,
                                               const float* __restrict__ b1,
                                               const float* __restrict__ w2) {
    __shared__ float s1[256], sb[256], s2[256];
    int jc = blockIdx.x & 7, tg = blockIdx.x >> 3;
    int tid = threadIdx.x;
    int j = jc * 256 + tid;
    s1[tid] = w1[j]; sb[tid] = b1[j]; s2[tid] = w2[j];
    __syncthreads();
    int base = tg * 2048 + tid * 8;
    float dv[8];
    *(float4*)dv = *(const float4*)(dens + base);
    *(float4*)(dv + 4) = *(const float4*)(dens + base + 4);
    float acc[8] = {};
#pragma unroll 4
    for (int jj = 0; jj < 256; jj++) {
        float a = s1[jj], bb = sb[jj], c = s2[jj];
#pragma unroll
        for (int u = 0; u < 8; u++) {
            float h = fmaf(dv[u], a, bb);
            acc[u] = fmaf(fmaxf(h, 0.f), c, acc[u]);
        }
    }
#pragma unroll
    for (int u = 0; u < 8; u++) atomicAdd(&g_dbias[base + u], acc[u]);
}

// ---------------- kernel 4: score GEMM via mma.sync (bf16 x3 split) ----------
#define APLN 6144      // elements per A plane (128 rows * 48)
#define BPLN 3072      // elements per B plane (64 rows * 48)
#define BBASE 18432    // element offset of B region
#define SCORE_SMEM 57344

__global__ void __launch_bounds__(256, 1) k_score_tc(const float* __restrict__ x) {
    extern __shared__ char smem[];
    float* sSf  = (float*)smem;                    // reused after MMA: [64][136]
    float* sqbi = (float*)(smem + 55296);
    float* sdb  = (float*)(smem + 55552);

    int tid = threadIdx.x, wid = tid >> 5, lane = tid & 31;
    int b = blockIdx.x >> 5, tile = blockIdx.x & 31;
    int n0 = tile << 7;
    int arow = (wid << 4) + (lane >> 2);
    int rowg = tid >> 1;
    int kb = (tid & 1) << 4;
    const float* xp = x + ((size_t)(b * N + n0 + rowg)) * D + kb;
    int bq = tid >> 2, bko = (tid & 3) << 3;

    float acc[8][4] = {};
    float4 v[4];
    uint4 bw[3];

    auto store_chunk = [&]() {
#pragma unroll
        for (int f = 0; f < 4; f++) {
            float4 w = v[f];
            uint32_t p0 = packbf(w.x, w.y), q0 = packbf(w.z, w.w);
            float rx = w.x - loff(p0), ry = w.y - hiff(p0);
            float rz = w.z - loff(q0), rw = w.w - hiff(q0);
            uint32_t p1 = packbf(rx, ry), q1 = packbf(rz, rw);
            float sx = rx - loff(p1), sy = ry - hiff(p1);
            float sz = rz - loff(q1), sw = rw - hiff(q1);
            uint32_t p2 = packbf(sx, sy), q2 = packbf(sz, sw);
            int off = rowg * 48 + kb + f * 4;
            *(uint2*)(smem + (size_t)off * 2)              = make_uint2(p0, q0);
            *(uint2*)(smem + (size_t)(APLN + off) * 2)     = make_uint2(p1, q1);
            *(uint2*)(smem + (size_t)(2 * APLN + off) * 2) = make_uint2(p2, q2);
        }
#pragma unroll
        for (int i = 0; i < 3; i++)
            *(uint4*)(smem + (size_t)(BBASE + i * BPLN + bq * 48 + bko) * 2) = bw[i];
    };

    auto do_mma = [&]() {
#pragma unroll
        for (int s = 0; s < 2; s++) {
            int kr = (s << 4) + ((lane & 3) << 1);
            uint32_t bf[3][8][2];
#pragma unroll
            for (int p = 0; p < 3; p++)
#pragma unroll
                for (int j = 0; j < 8; j++) {
                    int n = (j << 3) + (lane >> 2);
                    const char* bp = smem + (size_t)(BBASE + p * BPLN + n * 48) * 2;
                    bf[p][j][0] = *(const uint32_t*)(bp + kr * 2);
                    bf[p][j][1] = *(const uint32_t*)(bp + (kr + 8) * 2);
                }
            uint32_t af[3][4];
#pragma unroll
            for (int p = 0; p < 3; p++) {
                const char* ap = smem + (size_t)(p * APLN + arow * 48) * 2;
                af[p][0] = *(const uint32_t*)(ap + kr * 2);
                af[p][1] = *(const uint32_t*)(ap + (48 * 8 + kr) * 2);
                af[p][2] = *(const uint32_t*)(ap + (kr + 8) * 2);
                af[p][3] = *(const uint32_t*)(ap + (48 * 8 + kr + 8) * 2);
            }
#pragma unroll
            for (int j = 0; j < 8; j++) {
                mma16816(acc[j], af[0], bf[0][j]);
                mma16816(acc[j], af[0], bf[1][j]);
                mma16816(acc[j], af[1], bf[0][j]);
                mma16816(acc[j], af[1], bf[1][j]);
                mma16816(acc[j], af[0], bf[2][j]);
                mma16816(acc[j], af[2], bf[0][j]);
            }
        }
    };

    // prologue: load chunk 0
#pragma unroll
    for (int f = 0; f < 4; f++) v[f] = *(const float4*)(xp + f * 4);
#pragma unroll
    for (int i = 0; i < 3; i++)
        bw[i] = *(const uint4*)(g_QWb + (size_t)i * 65536 + bq * D + bko);
    store_chunk();
    __syncthreads();

    for (int c = 0; c < 32; c++) {
        if (c + 1 < 32) {
#pragma unroll
            for (int f = 0; f < 4; f++)
                v[f] = *(const float4*)(xp + (c + 1) * 32 + f * 4);
#pragma unroll
            for (int i = 0; i < 3; i++)
                bw[i] = *(const uint4*)(g_QWb + (size_t)i * 65536 + bq * D + (c + 1) * 32 + bko);
        }
        do_mma();
        __syncthreads();
        if (c + 1 < 32) { store_chunk(); __syncthreads(); }
    }

    // ---- epilogue: bias, stage to smem, coalesced store, softmax partials ---
    if (tid < 64) sqbi[tid] = g_qbi[tid];
    else if (tid < 192) sdb[tid - 64] = g_dbias[b * N + n0 + (tid - 64)];
    __syncthreads();

    float db0 = sdb[arow], db1 = sdb[arow + 8];
#pragma unroll
    for (int j = 0; j < 8; j++) {
        int q0 = (j << 3) + ((lane & 3) << 1);
        float t0 = sqbi[q0], t1 = sqbi[q0 + 1];
        sSf[q0 * 136 + arow]           = fmaf(acc[j][0], 0.03125f, t0 + db0);
        sSf[(q0 + 1) * 136 + arow]     = fmaf(acc[j][1], 0.03125f, t1 + db0);
        sSf[q0 * 136 + arow + 8]       = fmaf(acc[j][2], 0.03125f, t0 + db1);
        sSf[(q0 + 1) * 136 + arow + 8] = fmaf(acc[j][3], 0.03125f, t1 + db1);
    }
    __syncthreads();

    int q = tid >> 2, sg = tid & 3;
    float* srow = sSf + q * 136 + sg * 32;
    float* gdst = g_S + (((size_t)(b * NQ + q)) << 12) + n0 + sg * 32;
#pragma unroll
    for (int t = 0; t < 8; t++)
        *(float4*)(gdst + t * 4) = *(float4*)(srow + t * 4);

    float m = -1e30f;
#pragma unroll
    for (int i = 0; i < 32; i++) m = fmaxf(m, srow[i]);
    m = fmaxf(m, __shfl_xor_sync(~0u, m, 1));
    m = fmaxf(m, __shfl_xor_sync(~0u, m, 2));
    float z = 0.f;
#pragma unroll
    for (int i = 0; i < 32; i++) z += expf(srow[i] - m);
    z += __shfl_xor_sync(~0u, z, 1);
    z += __shfl_xor_sync(~0u, z, 2);
    if (sg == 0) {
        g_pmax[(b * 32 + tile) * NQ + q] = m;
        g_psum[(b * 32 + tile) * NQ + q] = z;
    }
}

// ---------------- kernel 5: combine partials -> c ----------------------------
__global__ void k_combine() {
    int t = blockIdx.x * 256 + threadIdx.x;   // < 512
    int b = t >> 6, q = t & 63;
    float M = -1e30f;
#pragma unroll 8
    for (int tl = 0; tl < 32; tl++)
        M = fmaxf(M, g_pmax[(b * 32 + tl) * NQ + q]);
    float Z = 0.f;
#pragma unroll 8
    for (int tl = 0; tl < 32; tl++)
        Z += g_psum[(b * 32 + tl) * NQ + q] * expf(g_pmax[(b * 32 + tl) * NQ + q] - M);
    g_c[b * NQ + q] = M + logf(Z);
}

// ---------------- kernel 6: importance (log-domain) --------------------------
__global__ void k_imp() {
    __shared__ float sc[NQ];
    int t = blockIdx.x * 256 + threadIdx.x;
    int b = t >> 12;
    if (threadIdx.x < NQ) sc[threadIdx.x] = g_c[b * NQ + threadIdx.x];
    __syncthreads();
    int n = t & (N - 1);
    const float* Sp = g_S + ((size_t)(b * NQ) << 12) + n;
    float best = -1e30f;
#pragma unroll 8
    for (int q = 0; q < NQ; q++) best = fmaxf(best, Sp[(size_t)q << 12] - sc[q]);
    g_imp[t] = best;
}

// ---------------- kernel 7: exact rank (stable top-k) ------------------------
__global__ void __launch_bounds__(256) k_rank() {
    __shared__ unsigned long long key[N];
    int b   = blockIdx.x >> 4;
    int seg = blockIdx.x & 15;
    int tid = threadIdx.x;
    for (int i = tid; i < N; i += 256) {
        unsigned u = __float_as_uint(g_imp[b * N + i]);
        u ^= ((unsigned)(((int)u) >> 31)) | 0x80000000u;
        key[i] = ((unsigned long long)u << 12) | (unsigned)(N - 1 - i);
    }
    __syncthreads();
    int i = seg * 256 + tid;
    unsigned long long ki = key[i];
    int r = 0;
#pragma unroll 8
    for (int j = 0; j < N; j++) r += (key[j] > ki);
    g_flag[b * N + i] = (r < TOPK) ? 1 : 0;
}

// ---------------- kernel 8: compact selected indices -------------------------
__global__ void k_compact() {
    __shared__ unsigned words[N / 32];
    __shared__ int pre[N / 32];
    int b   = blockIdx.x;
    int tid = threadIdx.x;
#pragma unroll
    for (int cc = 0; cc < N / 1024; cc++) {
        int gi = cc * 1024 + tid;
        unsigned bal = __ballot_sync(~0u, g_flag[b * N + gi]);
        if ((tid & 31) == 0) words[gi >> 5] = bal;
    }
    __syncthreads();
    if (tid == 0) {
        int s = 0;
        for (int w = 0; w < N / 32; w++) { pre[w] = s; s += __popc(words[w]); }
    }
    __syncthreads();
#pragma unroll
    for (int cc = 0; cc < N / 1024; cc++) {
        int gi = cc * 1024 + tid;
        unsigned w = words[gi >> 5];
        if ((w >> (gi & 31)) & 1u) {
            int slot = pre[gi >> 5] + __popc(w & ((1u << (gi & 31)) - 1u));
            g_idx[b * TOPK + slot] = gi;
        }
    }
}

// ---------------- kernel 9: gather selected rows -----------------------------
__global__ void k_gather(const float* __restrict__ x, float* __restrict__ out) {
    int row = blockIdx.x;
    int b   = row >> 10;
    int i   = g_idx[row];
    const float4* src = (const float4*)(x + ((size_t)(b * N + i)) * D);
    float4* dst = (float4*)(out + (size_t)row * D);
    dst[threadIdx.x] = src[threadIdx.x];
}

// ---------------- launch -----------------------------------------------------
extern "C" void kernel_launch(void* const* d_in, const int* in_sizes, int n_in,
                              void* d_out, int out_size) {
    const float* tf   = (const float*)d_in[0];
    const float* dens = (const float*)d_in[1];
    const float* qe   = (const float*)d_in[2];
    const float* kw   = (const float*)d_in[3];
    const float* kb   = (const float*)d_in[4];
    const float* w1   = (const float*)d_in[5];
    const float* b1   = (const float*)d_in[6];
    const float* w2   = (const float*)d_in[7];
    const float* b2   = (const float*)d_in[8];
    float* out = (float*)d_out;

    cudaFuncSetAttribute(k_score_tc, cudaFuncAttributeMaxDynamicSharedMemorySize, SCORE_SMEM);

    k_init<<<129, 256>>>(qe, kb, b2);
    k_qw<<<64, 256>>>(qe, kw);
    k_split<<<256, 256>>>();
    k_dbias<<<128, 256>>>(dens, w1, b1, w2);
    k_score_tc<<<256, 256, SCORE_SMEM>>>(tf);
    k_combine<<<2, 256>>>();
    k_imp<<<B * N / 256, 256>>>();
    k_rank<<<B * 16, 256>>>();
    k_compact<<<B, 1024>>>();
    k_gather<<<B * TOPK, 256>>>(tf, out);
}

// round 5
// speedup vs baseline: 2.2217x; 1.1118x over previous
#include <cuda_runtime.h>
#include <cuda_bf16.h>
#include <cstdint>

#define B 8
#define N 4096
#define D 1024
#define H 1024
#define NQ 64
#define H2 2048
#define TOPK 1024

// ---------------- scratch ----------------------------------------------------
__device__ __align__(16) float g_QWt[2][NQ * D];  // tf32 planes of QW [q][d]
__device__ float g_qbi[NQ];            // qb/32 + b2
__device__ float g_dbias[B * N];
__device__ float g_S[B * NQ * N];
__device__ float g_pmax[B * 32 * NQ];
__device__ float g_psum[B * 32 * NQ];
__device__ float g_c[B * NQ];
__device__ float g_imp[B * N];
__device__ int   g_flag[B * N];
__device__ int   g_idx[B * TOPK];
__device__ float g_C1, g_C2;
__device__ int   g_bz;

// ---------------- helpers ----------------------------------------------------
__device__ __forceinline__ uint32_t cvt_tf32(float v) {
    uint32_t r;
    asm("cvt.rna.tf32.f32 %0, %1;" : "=r"(r) : "f"(v));
    return r;
}
__device__ __forceinline__ void mma_tf32(float* d, const uint32_t* a, uint32_t b0, uint32_t b1) {
    asm volatile("mma.sync.aligned.m16n8k8.row.col.f32.tf32.tf32.f32 "
        "{%0,%1,%2,%3}, {%4,%5,%6,%7}, {%8,%9}, {%0,%1,%2,%3};"
        : "+f"(d[0]), "+f"(d[1]), "+f"(d[2]), "+f"(d[3])
        : "r"(a[0]), "r"(a[1]), "r"(a[2]), "r"(a[3]), "r"(b0), "r"(b1));
}

// ---------------- kernel 0: init (qbi + density consts) ----------------------
__global__ void k_init(const float* __restrict__ qe, const float* __restrict__ kb,
                       const float* __restrict__ b2, const float* __restrict__ w1,
                       const float* __restrict__ b1, const float* __restrict__ w2) {
    int tid = threadIdx.x;
    if (blockIdx.x == 0) {
        int w = tid >> 5, l = tid & 31;
        float b2v = b2[0];
#pragma unroll
        for (int qi = 0; qi < 8; qi++) {
            int q = w * 8 + qi;
            float acc = 0.f;
#pragma unroll
            for (int k = 0; k < 32; k++)
                acc = fmaf(qe[(size_t)q * H + k * 32 + l], kb[k * 32 + l], acc);
#pragma unroll
            for (int o = 16; o; o >>= 1) acc += __shfl_xor_sync(~0u, acc, o);
            if (l == 0) g_qbi[q] = acc * 0.03125f + b2v;
        }
    } else {
        __shared__ float r1[256], r2[256];
        __shared__ int rz[256];
        float c1 = 0.f, c2 = 0.f; int bz = 1;
        for (int j = tid; j < H2; j += 256) {
            float a = w1[j], c = w2[j];
            if (a > 0.f) c1 += a * c; else c2 += a * c;
            if (b1[j] != 0.f) bz = 0;
        }
        r1[tid] = c1; r2[tid] = c2; rz[tid] = bz;
        __syncthreads();
        for (int o = 128; o; o >>= 1) {
            if (tid < o) { r1[tid] += r1[tid + o]; r2[tid] += r2[tid + o]; rz[tid] &= rz[tid + o]; }
            __syncthreads();
        }
        if (tid == 0) { g_C1 = r1[0]; g_C2 = r2[0]; g_bz = rz[0]; }
    }
}

// ---------------- kernel 1: QW GEMM -> tf32 planes ---------------------------
__global__ void __launch_bounds__(256) k_qw(const float* __restrict__ qe,
                                            const float* __restrict__ kw) {
    __shared__ float skw[8][68];
    __shared__ float sqt[64][65];
    int d0 = blockIdx.x * 8;
    int tid = threadIdx.x;
    int q = tid & 63, dp = tid >> 6;   // dp 0..3
    float acc0 = 0.f, acc1 = 0.f;
    for (int k0 = 0; k0 < H; k0 += 64) {
#pragma unroll
        for (int r = 0; r < 2; r++) {
            int idx = tid + 256 * r;
            skw[idx >> 6][idx & 63] = kw[(size_t)(d0 + (idx >> 6)) * H + k0 + (idx & 63)];
        }
#pragma unroll
        for (int r = 0; r < 4; r++) {
            int idx = tid + 256 * r;
            int row = idx >> 4, c4 = (idx & 15) * 4;
            float4 v = *(const float4*)(qe + (size_t)row * H + k0 + c4);
            sqt[c4 + 0][row] = v.x; sqt[c4 + 1][row] = v.y;
            sqt[c4 + 2][row] = v.z; sqt[c4 + 3][row] = v.w;
        }
        __syncthreads();
#pragma unroll 8
        for (int k = 0; k < 64; k++) {
            float qv = sqt[k][q];
            acc0 = fmaf(skw[dp][k], qv, acc0);
            acc1 = fmaf(skw[dp + 4][k], qv, acc1);
        }
        __syncthreads();
    }
    uint32_t t0 = cvt_tf32(acc0);
    uint32_t t1 = cvt_tf32(acc0 - __uint_as_float(t0));
    g_QWt[0][(size_t)q * D + d0 + dp] = __uint_as_float(t0);
    g_QWt[1][(size_t)q * D + d0 + dp] = __uint_as_float(t1);
    t0 = cvt_tf32(acc1);
    t1 = cvt_tf32(acc1 - __uint_as_float(t0));
    g_QWt[0][(size_t)q * D + d0 + dp + 4] = __uint_as_float(t0);
    g_QWt[1][(size_t)q * D + d0 + dp + 4] = __uint_as_float(t1);
}

// ---------------- kernel 2: density bias -------------------------------------
__global__ void k_db(const float* __restrict__ dens, const float* __restrict__ w1,
                     const float* __restrict__ b1, const float* __restrict__ w2) {
    int t = blockIdx.x * 256 + threadIdx.x;
    float d = dens[t];
    if (g_bz) {
        g_dbias[t] = d * (d >= 0.f ? g_C1 : g_C2);
    } else {
        float acc = 0.f;
        for (int j = 0; j < H2; j++)
            acc = fmaf(fmaxf(fmaf(d, w1[j], b1[j]), 0.f), w2[j], acc);
        g_dbias[t] = acc;
    }
}

// ---------------- kernel 3: score GEMM via tf32 mma (2-plane, 3 terms) -------
// float offsets within smem
#define A0_OFF 0
#define A1_OFF 4608
#define B0_OFF 9216
#define B1_OFF 11776
#define QBI_OFF 14336
#define SDB_OFF 14400
#define SCORE_SMEM 58368

__global__ void __launch_bounds__(256, 2) k_score_tc(const float* __restrict__ x) {
    extern __shared__ float sm[];
    int tid = threadIdx.x, wid = tid >> 5, lane = tid & 31;
    int b = blockIdx.x >> 5, tile = blockIdx.x & 31;
    int n0 = tile << 7;
    int arow = (wid << 4) + (lane >> 2);
    int rowg = tid >> 1;
    int kb = (tid & 1) << 4;
    const float* xp = x + ((size_t)(b * N + n0 + rowg)) * D + kb;
    int bn = tid >> 2, bs = tid & 3;
    const float* bp0 = g_QWt[0] + (size_t)bn * D + bs * 8;
    const float* bp1 = g_QWt[1] + (size_t)bn * D + bs * 8;

    float acc[8][4] = {};
    float4 v[4];
    float4 va0, vb0, va1, vb1;

    auto load_chunk = [&](int c) {
#pragma unroll
        for (int f = 0; f < 4; f++) v[f] = *(const float4*)(xp + c * 32 + f * 4);
        va0 = *(const float4*)(bp0 + c * 32); vb0 = *(const float4*)(bp0 + c * 32 + 4);
        va1 = *(const float4*)(bp1 + c * 32); vb1 = *(const float4*)(bp1 + c * 32 + 4);
    };

    auto store_chunk = [&]() {
#pragma unroll
        for (int f = 0; f < 4; f++) {
            float4 w = v[f];
            uint32_t x0 = cvt_tf32(w.x), y0 = cvt_tf32(w.y), z0 = cvt_tf32(w.z), w0 = cvt_tf32(w.w);
            uint32_t x1 = cvt_tf32(w.x - __uint_as_float(x0));
            uint32_t y1 = cvt_tf32(w.y - __uint_as_float(y0));
            uint32_t z1 = cvt_tf32(w.z - __uint_as_float(z0));
            uint32_t w1v = cvt_tf32(w.w - __uint_as_float(w0));
            int off = rowg * 36 + kb + f * 4;
            *(uint4*)(sm + A0_OFF + off) = make_uint4(x0, y0, z0, w0);
            *(uint4*)(sm + A1_OFF + off) = make_uint4(x1, y1, z1, w1v);
        }
        int boff = bn * 40 + bs * 8;
        *(float4*)(sm + B0_OFF + boff)     = make_float4(va0.x, vb0.x, va0.y, vb0.y);
        *(float4*)(sm + B0_OFF + boff + 4) = make_float4(va0.z, vb0.z, va0.w, vb0.w);
        *(float4*)(sm + B1_OFF + boff)     = make_float4(va1.x, vb1.x, va1.y, vb1.y);
        *(float4*)(sm + B1_OFF + boff + 4) = make_float4(va1.z, vb1.z, va1.w, vb1.w);
    };

    auto do_mma = [&]() {
#pragma unroll
        for (int s = 0; s < 4; s++) {
            int kc = s * 8 + (lane & 3);
            const float* a0p = sm + A0_OFF + arow * 36 + kc;
            const float* a1p = sm + A1_OFF + arow * 36 + kc;
            uint32_t af0[4] = { __float_as_uint(a0p[0]), __float_as_uint(a0p[8 * 36]),
                                __float_as_uint(a0p[4]), __float_as_uint(a0p[8 * 36 + 4]) };
            uint32_t af1[4] = { __float_as_uint(a1p[0]), __float_as_uint(a1p[8 * 36]),
                                __float_as_uint(a1p[4]), __float_as_uint(a1p[8 * 36 + 4]) };
#pragma unroll
            for (int j = 0; j < 8; j++) {
                int n = j * 8 + (lane >> 2);
                float2 b0 = *(const float2*)(sm + B0_OFF + n * 40 + s * 8 + (lane & 3) * 2);
                float2 b1 = *(const float2*)(sm + B1_OFF + n * 40 + s * 8 + (lane & 3) * 2);
                mma_tf32(acc[j], af0, __float_as_uint(b0.x), __float_as_uint(b0.y));
                mma_tf32(acc[j], af0, __float_as_uint(b1.x), __float_as_uint(b1.y));
                mma_tf32(acc[j], af1, __float_as_uint(b0.x), __float_as_uint(b0.y));
            }
        }
    };

    load_chunk(0);
    store_chunk();
    __syncthreads();

    for (int c = 0; c < 32; c++) {
        if (c + 1 < 32) load_chunk(c + 1);
        do_mma();
        __syncthreads();
        if (c + 1 < 32) { store_chunk(); __syncthreads(); }
    }

    // ---- epilogue: bias, stage, coalesced store, softmax partials -----------
    if (tid < 64) sm[QBI_OFF + tid] = g_qbi[tid];
    else if (tid < 192) sm[SDB_OFF + tid - 64] = g_dbias[b * N + n0 + (tid - 64)];
    __syncthreads();

    float db0 = sm[SDB_OFF + arow], db1 = sm[SDB_OFF + arow + 8];
    float sS[1]; (void)sS;
#pragma unroll
    for (int j = 0; j < 8; j++) {
        int q0 = (j << 3) + ((lane & 3) << 1);
        float t0 = sm[QBI_OFF + q0], t1 = sm[QBI_OFF + q0 + 1];
        sm[q0 * 136 + arow]           = fmaf(acc[j][0], 0.03125f, t0 + db0);
        sm[(q0 + 1) * 136 + arow]     = fmaf(acc[j][1], 0.03125f, t1 + db0);
        sm[q0 * 136 + arow + 8]       = fmaf(acc[j][2], 0.03125f, t0 + db1);
        sm[(q0 + 1) * 136 + arow + 8] = fmaf(acc[j][3], 0.03125f, t1 + db1);
    }
    __syncthreads();

    int q = tid >> 2, sg = tid & 3;
    float* srow = sm + q * 136 + sg * 32;
    float* gdst = g_S + (((size_t)(b * NQ + q)) << 12) + n0 + sg * 32;
#pragma unroll
    for (int t = 0; t < 8; t++)
        *(float4*)(gdst + t * 4) = *(float4*)(srow + t * 4);

    float m = -1e30f;
#pragma unroll
    for (int i = 0; i < 32; i++) m = fmaxf(m, srow[i]);
    m = fmaxf(m, __shfl_xor_sync(~0u, m, 1));
    m = fmaxf(m, __shfl_xor_sync(~0u, m, 2));
    float z = 0.f;
#pragma unroll
    for (int i = 0; i < 32; i++) z += expf(srow[i] - m);
    z += __shfl_xor_sync(~0u, z, 1);
    z += __shfl_xor_sync(~0u, z, 2);
    if (sg == 0) {
        g_pmax[(b * 32 + tile) * NQ + q] = m;
        g_psum[(b * 32 + tile) * NQ + q] = z;
    }
}

// ---------------- kernel 4: combine partials -> c ----------------------------
__global__ void k_combine() {
    int t = blockIdx.x * 256 + threadIdx.x;
    int b = t >> 6, q = t & 63;
    float M = -1e30f;
#pragma unroll 8
    for (int tl = 0; tl < 32; tl++)
        M = fmaxf(M, g_pmax[(b * 32 + tl) * NQ + q]);
    float Z = 0.f;
#pragma unroll 8
    for (int tl = 0; tl < 32; tl++)
        Z += g_psum[(b * 32 + tl) * NQ + q] * expf(g_pmax[(b * 32 + tl) * NQ + q] - M);
    g_c[b * NQ + q] = M + logf(Z);
}

// ---------------- kernel 5: importance (log-domain) --------------------------
__global__ void k_imp() {
    __shared__ float sc[NQ];
    int t = blockIdx.x * 256 + threadIdx.x;
    int b = t >> 12;
    if (threadIdx.x < NQ) sc[threadIdx.x] = g_c[b * NQ + threadIdx.x];
    __syncthreads();
    int n = t & (N - 1);
    const float* Sp = g_S + ((size_t)(b * NQ) << 12) + n;
    float best = -1e30f;
#pragma unroll 8
    for (int q = 0; q < NQ; q++) best = fmaxf(best, Sp[(size_t)q << 12] - sc[q]);
    g_imp[t] = best;
}

// ---------------- kernel 6: exact rank (stable top-k) ------------------------
__global__ void __launch_bounds__(256) k_rank() {
    __shared__ unsigned long long key[N];
    int b   = blockIdx.x >> 4;
    int seg = blockIdx.x & 15;
    int tid = threadIdx.x;
    for (int i = tid; i < N; i += 256) {
        unsigned u = __float_as_uint(g_imp[b * N + i]);
        u ^= ((unsigned)(((int)u) >> 31)) | 0x80000000u;
        key[i] = ((unsigned long long)u << 12) | (unsigned)(N - 1 - i);
    }
    __syncthreads();
    int i = seg * 256 + tid;
    unsigned long long ki = key[i];
    int r = 0;
#pragma unroll 8
    for (int j = 0; j < N; j++) r += (key[j] > ki);
    g_flag[b * N + i] = (r < TOPK) ? 1 : 0;
}

// ---------------- kernel 7: compact selected indices -------------------------
__global__ void k_compact() {
    __shared__ unsigned words[N / 32];
    __shared__ int pre[N / 32];
    int b   = blockIdx.x;
    int tid = threadIdx.x;
#pragma unroll
    for (int cc = 0; cc < N / 1024; cc++) {
        int gi = cc * 1024 + tid;
        unsigned bal = __ballot_sync(~0u, g_flag[b * N + gi]);
        if ((tid & 31) == 0) words[gi >> 5] = bal;
    }
    __syncthreads();
    if (tid == 0) {
        int s = 0;
        for (int w = 0; w < N / 32; w++) { pre[w] = s; s += __popc(words[w]); }
    }
    __syncthreads();
#pragma unroll
    for (int cc = 0; cc < N / 1024; cc++) {
        int gi = cc * 1024 + tid;
        unsigned w = words[gi >> 5];
        if ((w >> (gi & 31)) & 1u) {
            int slot = pre[gi >> 5] + __popc(w & ((1u << (gi & 31)) - 1u));
            g_idx[b * TOPK + slot] = gi;
        }
    }
}

// ---------------- kernel 8: gather selected rows -----------------------------
__global__ void k_gather(const float* __restrict__ x, float* __restrict__ out) {
    int row = blockIdx.x;
    int b   = row >> 10;
    int i   = g_idx[row];
    const float4* src = (const float4*)(x + ((size_t)(b * N + i)) * D);
    float4* dst = (float4*)(out + (size_t)row * D);
    dst[threadIdx.x] = src[threadIdx.x];
}

// ---------------- launch -----------------------------------------------------
extern "C" void kernel_launch(void* const* d_in, const int* in_sizes, int n_in,
                              void* d_out, int out_size) {
    const float* tf   = (const float*)d_in[0];
    const float* dens = (const float*)d_in[1];
    const float* qe   = (const float*)d_in[2];
    const float* kw   = (const float*)d_in[3];
    const float* kb   = (const float*)d_in[4];
    const float* w1   = (const float*)d_in[5];
    const float* b1   = (const float*)d_in[6];
    const float* w2   = (const float*)d_in[7];
    const float* b2   = (const float*)d_in[8];
    float* out = (float*)d_out;

    cudaFuncSetAttribute(k_score_tc, cudaFuncAttributeMaxDynamicSharedMemorySize,
                         SCORE_SMEM * (int)sizeof(float) / 1);
    cudaFuncSetAttribute(k_score_tc, cudaFuncAttributeMaxDynamicSharedMemorySize, SCORE_SMEM);

    k_init<<<2, 256>>>(qe, kb, b2, w1, b1, w2);
    k_qw<<<128, 256>>>(qe, kw);
    k_db<<<128, 256>>>(dens, w1, b1, w2);
    k_score_tc<<<256, 256, SCORE_SMEM>>>(tf);
    k_combine<<<2, 256>>>();
    k_imp<<<B * N / 256, 256>>>();
    k_rank<<<B * 16, 256>>>();
    k_compact<<<B, 1024>>>();
    k_gather<<<B * TOPK, 256>>>(tf, out);
}